// round 1
// baseline (speedup 1.0000x reference)
#include <cuda_runtime.h>
#include <cuda_bf16.h>
#include <cstdint>

// ---------------------------------------------------------------------------
// Problem constants
// ---------------------------------------------------------------------------
#define BATCH     256
#define D_MODEL   2048
#define D_STATE   128
#define D_CONV    4
#define D_SSM     4096
#define NHEADS    64
#define HEADDIM   64
#define CONV_DIM  (D_SSM + 2 * D_STATE)            // 4352
#define D_IN_PROJ (2 * D_SSM + 2 * D_STATE + NHEADS) // 8512

// Output layout in d_out (concatenated tuple, fp32):
//   [0 : 256*2048)                      out
//   [OUT_N : OUT_N + 256*4352*4)        conv_state
//   [CONV_END : +256*64*64*128)         ssm_state
#define OUT_N   (BATCH * D_MODEL)                  // 524288
#define CONV_N  (BATCH * CONV_DIM * D_CONV)        // 4456448
#define SSM_OFF (OUT_N + CONV_N)                   // 4980736

// ---------------------------------------------------------------------------
// Scratch (no allocation allowed -> __device__ globals)
// ---------------------------------------------------------------------------
__device__ float g_zxbcdt[(size_t)BATCH * D_IN_PROJ]; // 8.7 MB
__device__ float g_act[(size_t)BATCH * CONV_DIM];     // 4.5 MB  (post-conv silu xBC)
__device__ float g_yz[(size_t)BATCH * D_SSM];         // 4.2 MB  (y * silu(z))

// ---------------------------------------------------------------------------
// Packed f32x2 helpers (Blackwell) — exact fp32 FMA semantics, 2x issue rate
// ---------------------------------------------------------------------------
__device__ __forceinline__ unsigned long long pack2(float lo, float hi) {
    unsigned long long r;
    asm("mov.b64 %0, {%1, %2};" : "=l"(r) : "f"(lo), "f"(hi));
    return r;
}
__device__ __forceinline__ unsigned long long dup2(float v) {
    unsigned long long r;
    asm("mov.b64 %0, {%1, %1};" : "=l"(r) : "f"(v));
    return r;
}
__device__ __forceinline__ void unpack2(unsigned long long v, float& lo, float& hi) {
    asm("mov.b64 {%0, %1}, %2;" : "=f"(lo), "=f"(hi) : "l"(v));
}
__device__ __forceinline__ void fma2(unsigned long long& d, unsigned long long a,
                                     unsigned long long b) {
    asm("fma.rn.f32x2 %0, %1, %2, %0;" : "+l"(d) : "l"(a), "l"(b));
}

// ---------------------------------------------------------------------------
// GEMM: C[M,N] = A[M,K] @ B[N,K]^T   (both K-contiguous, "NT")
// Tile BM=128, BN=64, BK=16, 256 threads, 8x4 microtile per thread, f32x2.
// M % 128 == 0, N % 64 == 0, klen % 16 == 0 (all hold for our shapes).
// ---------------------------------------------------------------------------
#define GBM 128
#define GBN 64
#define GBK 16

template <bool ATOMIC>
__global__ __launch_bounds__(256) void gemm_nt_kernel(
    const float* __restrict__ A, const float* __restrict__ B,
    float* __restrict__ C, int M, int N, int K, int klen)
{
    __shared__ __align__(16) float As[GBK][GBM];
    __shared__ __align__(16) float Bs[GBK][GBN];

    const int tid = threadIdx.x;
    const int n0 = blockIdx.x * GBN;
    const int m0 = blockIdx.y * GBM;
    const int k0 = blockIdx.z * klen;

    // global load mapping
    const int am = tid >> 1;          // 0..127
    const int ak = (tid & 1) * 8;     // 0 or 8
    const int bn = tid >> 2;          // 0..63
    const int bk = (tid & 3) * 4;     // 0,4,8,12

    const float* Ag = A + (size_t)(m0 + am) * K + k0 + ak;
    const float* Bg = B + (size_t)(n0 + bn) * K + k0 + bk;

    // compute mapping
    const int tm = (tid & 15) * 8;    // row base (8 rows)
    const int tn = (tid >> 4) * 4;    // col base (4 cols)

    unsigned long long acc[8][2];
#pragma unroll
    for (int i = 0; i < 8; i++) { acc[i][0] = 0ULL; acc[i][1] = 0ULL; }

    for (int kt = 0; kt < klen; kt += GBK) {
        float4 a0 = *(const float4*)(Ag);
        float4 a1 = *(const float4*)(Ag + 4);
        float4 b0 = *(const float4*)(Bg);
        Ag += GBK; Bg += GBK;

        As[ak + 0][am] = a0.x; As[ak + 1][am] = a0.y;
        As[ak + 2][am] = a0.z; As[ak + 3][am] = a0.w;
        As[ak + 4][am] = a1.x; As[ak + 5][am] = a1.y;
        As[ak + 6][am] = a1.z; As[ak + 7][am] = a1.w;
        Bs[bk + 0][bn] = b0.x; Bs[bk + 1][bn] = b0.y;
        Bs[bk + 2][bn] = b0.z; Bs[bk + 3][bn] = b0.w;
        __syncthreads();

#pragma unroll
        for (int k = 0; k < GBK; k++) {
            float4 av0 = *(const float4*)&As[k][tm];
            float4 av1 = *(const float4*)&As[k][tm + 4];
            float4 bv  = *(const float4*)&Bs[k][tn];
            unsigned long long bp0 = pack2(bv.x, bv.y);
            unsigned long long bp1 = pack2(bv.z, bv.w);
            float a_[8] = {av0.x, av0.y, av0.z, av0.w, av1.x, av1.y, av1.z, av1.w};
#pragma unroll
            for (int i = 0; i < 8; i++) {
                unsigned long long ap = dup2(a_[i]);
                fma2(acc[i][0], ap, bp0);
                fma2(acc[i][1], ap, bp1);
            }
        }
        __syncthreads();
    }

#pragma unroll
    for (int i = 0; i < 8; i++) {
        float c0, c1, c2, c3;
        unpack2(acc[i][0], c0, c1);
        unpack2(acc[i][1], c2, c3);
        size_t off = (size_t)(m0 + tm + i) * N + n0 + tn;
        if (ATOMIC) {
            atomicAdd(&C[off + 0], c0);
            atomicAdd(&C[off + 1], c1);
            atomicAdd(&C[off + 2], c2);
            atomicAdd(&C[off + 3], c3);
        } else {
            *(float4*)(C + off) = make_float4(c0, c1, c2, c3);
        }
    }
}

// ---------------------------------------------------------------------------
// Conv step: per (b, c): roll state, apply depthwise conv + bias, silu.
// grid (17, 256) x 256 threads  (4352 = 17*256)
// ---------------------------------------------------------------------------
__global__ __launch_bounds__(256) void conv_kernel(
    const float* __restrict__ conv_in,  // [B, CONV_DIM, 4]
    const float* __restrict__ conv_w,   // [CONV_DIM, 4]
    const float* __restrict__ conv_b,   // [CONV_DIM]
    float* __restrict__ conv_out)       // d_out conv region
{
    const int c = blockIdx.x * 256 + threadIdx.x;   // < 4352
    const int b = blockIdx.y;
    const size_t idx = (size_t)b * CONV_DIM + c;

    float4 s = *(const float4*)(conv_in + idx * 4);
    float4 w = *(const float4*)(conv_w + (size_t)c * 4);
    float xin = g_zxbcdt[(size_t)b * D_IN_PROJ + D_SSM + c];

    float v = s.y * w.x + s.z * w.y + s.w * w.z + xin * w.w + conv_b[c];
    float act = v / (1.0f + expf(-v));   // silu

    *(float4*)(conv_out + idx * 4) = make_float4(s.y, s.z, s.w, xin);
    g_act[idx] = act;
}

// ---------------------------------------------------------------------------
// SSM fused kernel: one block per (h, b). 256 threads = 8 warps x 8 rows.
// state_new = state*dA + (dt*B[n])*x[p] ; y[p] = <state_new, C> + D*x[p]
// yz = y * silu(z) -> g_yz. state_new -> d_out ssm region.
// ---------------------------------------------------------------------------
__global__ __launch_bounds__(256) void ssm_kernel(
    const float* __restrict__ ssm_in,   // [B, H, P, N]
    const float* __restrict__ dt_bias,
    const float* __restrict__ A_log,
    const float* __restrict__ Dvec,
    float* __restrict__ ssm_out)
{
    const int h = blockIdx.x;
    const int b = blockIdx.y;
    const int tid = threadIdx.x;

    __shared__ __align__(16) float sB[D_STATE];
    __shared__ __align__(16) float sC[D_STATE];
    __shared__ float s_dt, s_dA, s_Dh;

    if (tid == 0) {
        float v = g_zxbcdt[(size_t)b * D_IN_PROJ + (2 * D_SSM + 2 * D_STATE) + h]
                  + dt_bias[h];
        float dt = fmaxf(v, 0.0f) + log1pf(expf(-fabsf(v)));   // softplus
        float A  = -expf(A_log[h]);
        s_dt = dt;
        s_dA = expf(dt * A);
        s_Dh = Dvec[h];
    }
    if (tid < D_STATE) {
        sB[tid] = g_act[(size_t)b * CONV_DIM + D_SSM + tid];
        sC[tid] = g_act[(size_t)b * CONV_DIM + D_SSM + D_STATE + tid];
    }
    __syncthreads();

    const float dt = s_dt, dA = s_dA, Dh = s_Dh;
    const int warp = tid >> 5, lane = tid & 31;

    const float* base_in  = ssm_in  + (((size_t)b * NHEADS + h) * HEADDIM) * D_STATE;
    float*       base_out = ssm_out + (((size_t)b * NHEADS + h) * HEADDIM) * D_STATE;

    const float4 bb = *(const float4*)&sB[lane * 4];
    const float4 cc = *(const float4*)&sC[lane * 4];

#pragma unroll
    for (int r = 0; r < 8; r++) {
        const int p = warp * 8 + r;
        float x = g_act[(size_t)b * CONV_DIM + h * HEADDIM + p];
        float xdt = x * dt;

        float4 st = *(const float4*)(base_in + (size_t)p * D_STATE + lane * 4);
        float n0 = st.x * dA + bb.x * xdt;
        float n1 = st.y * dA + bb.y * xdt;
        float n2 = st.z * dA + bb.z * xdt;
        float n3 = st.w * dA + bb.w * xdt;
        *(float4*)(base_out + (size_t)p * D_STATE + lane * 4) =
            make_float4(n0, n1, n2, n3);

        float ysum = n0 * cc.x + n1 * cc.y + n2 * cc.z + n3 * cc.w;
#pragma unroll
        for (int off = 16; off; off >>= 1)
            ysum += __shfl_xor_sync(0xffffffffu, ysum, off);

        if (lane == 0) {
            float y = ysum + Dh * x;
            float z = g_zxbcdt[(size_t)b * D_IN_PROJ + h * HEADDIM + p];
            float sz = z / (1.0f + expf(-z));
            g_yz[(size_t)b * D_SSM + h * HEADDIM + p] = y * sz;
        }
    }
}

// ---------------------------------------------------------------------------
// Zero the `out` region of d_out (needed before atomic split-K accumulation)
// ---------------------------------------------------------------------------
__global__ void zero_kernel(float* __restrict__ p, int n) {
    int i = blockIdx.x * blockDim.x + threadIdx.x;
    if (i < n) p[i] = 0.0f;
}

// ---------------------------------------------------------------------------
// Launch
// ---------------------------------------------------------------------------
extern "C" void kernel_launch(void* const* d_in, const int* in_sizes, int n_in,
                              void* d_out, int out_size)
{
    const float* hidden    = (const float*)d_in[0];  // [256,1,2048]
    const float* conv_in   = (const float*)d_in[1];  // [256,4352,4]
    const float* ssm_in    = (const float*)d_in[2];  // [256,64,64,128]
    const float* in_proj_w = (const float*)d_in[3];  // [8512,2048]
    const float* conv_w    = (const float*)d_in[4];  // [4352,4]
    const float* conv_b    = (const float*)d_in[5];  // [4352]
    const float* dt_bias   = (const float*)d_in[6];  // [64]
    const float* A_log     = (const float*)d_in[7];  // [64]
    const float* Dvec      = (const float*)d_in[8];  // [64]
    const float* out_w     = (const float*)d_in[9];  // [2048,4096]

    float* out_p  = (float*)d_out;
    float* conv_p = out_p + OUT_N;
    float* ssm_p  = out_p + SSM_OFF;

    float* zx;  cudaGetSymbolAddress((void**)&zx, g_zxbcdt);
    float* yz;  cudaGetSymbolAddress((void**)&yz, g_yz);

    // 0) zero out-proj output region (split-K atomics accumulate into it)
    zero_kernel<<<(OUT_N + 255) / 256, 256>>>(out_p, OUT_N);

    // 1) in_proj: zxbcdt[256,8512] = hidden[256,2048] @ in_proj_w^T
    {
        dim3 grid(D_IN_PROJ / GBN, BATCH / GBM, 1);   // (133, 2, 1)
        gemm_nt_kernel<false><<<grid, 256>>>(hidden, in_proj_w, zx,
                                             BATCH, D_IN_PROJ, D_MODEL, D_MODEL);
    }

    // 2) conv step
    {
        dim3 grid(CONV_DIM / 256, BATCH, 1);          // (17, 256)
        conv_kernel<<<grid, 256>>>(conv_in, conv_w, conv_b, conv_p);
    }

    // 3) fused SSM update + y*silu(z)
    {
        dim3 grid(NHEADS, BATCH, 1);                  // (64, 256)
        ssm_kernel<<<grid, 256>>>(ssm_in, dt_bias, A_log, Dvec, ssm_p);
    }

    // 4) out_proj: out[256,2048] = yz[256,4096] @ out_w^T  (split-K=8, atomic)
    {
        dim3 grid(D_MODEL / GBN, BATCH / GBM, 8);     // (32, 2, 8)
        gemm_nt_kernel<true><<<grid, 256>>>(yz, out_w, out_p,
                                            BATCH, D_MODEL, D_SSM, D_SSM / 8);
    }
}